// round 6
// baseline (speedup 1.0000x reference)
#include <cuda_runtime.h>
#include <cuda_bf16.h>

#define TPB  256
#define NBLK 128                       // 128 rows per block * 128 = 16384
#define SLOTF 20                       // floats per weight slot (80 B, conflict-free)
#define SMEM_BYTES (2048 * SLOTF * 4)  // 163840 B

static __device__ __forceinline__ unsigned long long pack2(float a) {
    unsigned long long r;
    asm("mov.b64 %0, {%1, %1};" : "=l"(r) : "f"(a));
    return r;
}
static __device__ __forceinline__ void unpack2(unsigned long long v, float& a, float& b) {
    asm("mov.b64 {%0, %1}, %2;" : "=f"(a), "=f"(b) : "l"(v));
}
static __device__ __forceinline__ unsigned long long ffma2(unsigned long long a,
                                                           unsigned long long b,
                                                           unsigned long long c) {
    unsigned long long d;
    asm("fma.rn.f32x2 %0, %1, %2, %3;" : "=l"(d) : "l"(a), "l"(b), "l"(c));
    return d;
}
static __device__ __forceinline__ unsigned long long fadd2(unsigned long long a,
                                                           unsigned long long b) {
    unsigned long long d;
    asm("add.rn.f32x2 %0, %1, %2;" : "=l"(d) : "l"(a), "l"(b));
    return d;
}

// Lane (rg = lane&3, seg = lane>>2): 4 rows (rg) x 256-h segment (seg).
// Weight slot for h: slot = (h&255)*8 + (h>>8), padded to 20 floats so the 8
// segs' concurrent LDS land on distinct 16B positions mod 128B (no conflicts).
__global__ void __launch_bounds__(TPB) fused_k(
    const float* __restrict__ x,
    const float* __restrict__ Wg, const float* __restrict__ bg,
    const float* __restrict__ Wp, const float* __restrict__ bp,
    const float* __restrict__ Wa, const float* __restrict__ ba,
    float* __restrict__ out)
{
    extern __shared__ float ws[];
    const int tid = threadIdx.x;

    // Stage packed weights: cols [0..3]=Wg, [4..7]=Wp, [8..12]=Wa, 13..15 = 0
    for (int idx = tid; idx < 2048 * 4; idx += TPB) {
        int h = idx >> 2, q = idx & 3;
        int slot = ((h & 255) << 3) | (h >> 8);
        float4 v;
        if (q == 0)      v = *(const float4*)(Wg + h * 4);
        else if (q == 1) v = *(const float4*)(Wp + h * 4);
        else if (q == 2) { const float* a = Wa + h * 5; v = make_float4(a[0], a[1], a[2], a[3]); }
        else             v = make_float4(Wa[h * 5 + 4], 0.f, 0.f, 0.f);
        *(float4*)(ws + slot * SLOTF + q * 4) = v;
    }
    __syncthreads();

    const int lane = tid & 31;
    const int warp = tid >> 5;
    const int rg   = lane & 3;
    const int seg  = lane >> 2;
    const int rowb = blockIdx.x * 128 + warp * 16 + rg * 4;   // 4 rows: rowb..rowb+3

    const float4* xr0 = (const float4*)(x + (size_t)(rowb + 0) * 2048 + seg * 256);
    const float4* xr1 = (const float4*)(x + (size_t)(rowb + 1) * 2048 + seg * 256);
    const float4* xr2 = (const float4*)(x + (size_t)(rowb + 2) * 2048 + seg * 256);
    const float4* xr3 = (const float4*)(x + (size_t)(rowb + 3) * 2048 + seg * 256);

    unsigned long long acc[4][7];
#pragma unroll
    for (int r = 0; r < 4; r++)
#pragma unroll
        for (int c = 0; c < 7; c++) acc[r][c] = 0ull;

#pragma unroll 2
    for (int ic = 0; ic < 64; ic++) {
        float4 xv0 = xr0[ic];
        float4 xv1 = xr1[ic];
        float4 xv2 = xr2[ic];
        float4 xv3 = xr3[ic];
#pragma unroll
        for (int j = 0; j < 4; j++) {
            int hl = (ic << 2) + j;                       // h within segment
            const float* wr = ws + ((hl << 3) | seg) * SLOTF;
            ulonglong2 wA = *(const ulonglong2*)(wr);     // cols 0..3
            ulonglong2 wB = *(const ulonglong2*)(wr + 4); // cols 4..7
            ulonglong2 wC = *(const ulonglong2*)(wr + 8); // cols 8..11
            unsigned long long wD = *(const unsigned long long*)(wr + 12); // 12,13

            float s0 = (j == 0) ? xv0.x : (j == 1) ? xv0.y : (j == 2) ? xv0.z : xv0.w;
            float s1 = (j == 0) ? xv1.x : (j == 1) ? xv1.y : (j == 2) ? xv1.z : xv1.w;
            float s2 = (j == 0) ? xv2.x : (j == 1) ? xv2.y : (j == 2) ? xv2.z : xv2.w;
            float s3 = (j == 0) ? xv3.x : (j == 1) ? xv3.y : (j == 2) ? xv3.z : xv3.w;
            unsigned long long x0 = pack2(s0), x1 = pack2(s1),
                               x2 = pack2(s2), x3 = pack2(s3);

            acc[0][0] = ffma2(x0, wA.x, acc[0][0]); acc[0][1] = ffma2(x0, wA.y, acc[0][1]);
            acc[0][2] = ffma2(x0, wB.x, acc[0][2]); acc[0][3] = ffma2(x0, wB.y, acc[0][3]);
            acc[0][4] = ffma2(x0, wC.x, acc[0][4]); acc[0][5] = ffma2(x0, wC.y, acc[0][5]);
            acc[0][6] = ffma2(x0, wD,   acc[0][6]);

            acc[1][0] = ffma2(x1, wA.x, acc[1][0]); acc[1][1] = ffma2(x1, wA.y, acc[1][1]);
            acc[1][2] = ffma2(x1, wB.x, acc[1][2]); acc[1][3] = ffma2(x1, wB.y, acc[1][3]);
            acc[1][4] = ffma2(x1, wC.x, acc[1][4]); acc[1][5] = ffma2(x1, wC.y, acc[1][5]);
            acc[1][6] = ffma2(x1, wD,   acc[1][6]);

            acc[2][0] = ffma2(x2, wA.x, acc[2][0]); acc[2][1] = ffma2(x2, wA.y, acc[2][1]);
            acc[2][2] = ffma2(x2, wB.x, acc[2][2]); acc[2][3] = ffma2(x2, wB.y, acc[2][3]);
            acc[2][4] = ffma2(x2, wC.x, acc[2][4]); acc[2][5] = ffma2(x2, wC.y, acc[2][5]);
            acc[2][6] = ffma2(x2, wD,   acc[2][6]);

            acc[3][0] = ffma2(x3, wA.x, acc[3][0]); acc[3][1] = ffma2(x3, wA.y, acc[3][1]);
            acc[3][2] = ffma2(x3, wB.x, acc[3][2]); acc[3][3] = ffma2(x3, wB.y, acc[3][3]);
            acc[3][4] = ffma2(x3, wC.x, acc[3][4]); acc[3][5] = ffma2(x3, wC.y, acc[3][5]);
            acc[3][6] = ffma2(x3, wD,   acc[3][6]);
        }
    }

    // Butterfly-reduce across the 8 segments (lane bits 2..4).
#pragma unroll
    for (int m = 4; m <= 16; m <<= 1) {
#pragma unroll
        for (int r = 0; r < 4; r++)
#pragma unroll
            for (int c = 0; c < 7; c++)
                acc[r][c] = fadd2(acc[r][c],
                                  __shfl_xor_sync(0xffffffffu, acc[r][c], m));
    }

    // Epilogue: lanes with seg<4 each finish one row (row = rowb + seg).
    if (seg < 4) {
        float v[14];
#pragma unroll
        for (int c = 0; c < 7; c++) unpack2(acc[seg][c], v[2 * c], v[2 * c + 1]);

        const float LOG2E = 1.4426950408889634f;
        float G[4], P[4], A[5];
#pragma unroll
        for (int c = 0; c < 4; c++) G[c] = v[c]     + __ldg(bg + c);
#pragma unroll
        for (int c = 0; c < 4; c++) P[c] = v[4 + c] + __ldg(bp + c);
#pragma unroll
        for (int c = 0; c < 5; c++) A[c] = v[8 + c] + __ldg(ba + c);

        float mg = fmaxf(fmaxf(G[0], G[1]), fmaxf(G[2], G[3]));
        float sg = 0.f;
#pragma unroll
        for (int c = 0; c < 4; c++) { G[c] = exp2f((G[c] - mg) * LOG2E); sg += G[c]; }
        float ig = 1.f / sg;
#pragma unroll
        for (int c = 0; c < 4; c++) G[c] *= ig;

        float mp = fmaxf(fmaxf(P[0], P[1]), fmaxf(P[2], P[3]));
        float sp = 0.f;
#pragma unroll
        for (int c = 0; c < 4; c++) { P[c] = exp2f((P[c] - mp) * LOG2E); sp += P[c]; }
        float ip = 1.f / sp;
#pragma unroll
        for (int c = 0; c < 4; c++) P[c] *= ip;

        float ma = fmaxf(fmaxf(fmaxf(A[0], A[1]), fmaxf(A[2], A[3])), A[4]);
        float sa = 0.f;
#pragma unroll
        for (int c = 0; c < 5; c++) { A[c] = exp2f((A[c] - ma) * LOG2E); sa += A[c]; }
        float ia = 1.f / sa;
#pragma unroll
        for (int c = 0; c < 5; c++) A[c] *= ia;

        float u0 = P[0] * G[0] + P[1] * G[1] + P[2] * G[2] + P[3] * G[3]; // stay
        float u1 = P[0] * G[1] + P[2] * G[3];                             // up
        float u2 = P[1] * G[0] + P[3] * G[2];                             // down

        float j0 = A[0] * (1.f - u0);
        float j1 = A[1] * (1.f - u1);
        float j2 = A[2] * (1.f - u2);
        float j3 = A[3];
        float j4 = A[4];
        float inv = 1.f / (j0 + j1 + j2 + j3 + j4);

        float* o = out + (size_t)(rowb + seg) * 5;
        o[0] = j0 * inv; o[1] = j1 * inv; o[2] = j2 * inv;
        o[3] = j3 * inv; o[4] = j4 * inv;
    }
}

extern "C" void kernel_launch(void* const* d_in, const int* in_sizes, int n_in,
                              void* d_out, int out_size) {
    const float* x  = (const float*)d_in[0];
    const float* Wg = (const float*)d_in[1];
    const float* bg = (const float*)d_in[2];
    const float* Wp = (const float*)d_in[3];
    const float* bp = (const float*)d_in[4];
    const float* Wa = (const float*)d_in[5];
    const float* ba = (const float*)d_in[6];
    float* out = (float*)d_out;

    cudaFuncSetAttribute(fused_k, cudaFuncAttributeMaxDynamicSharedMemorySize,
                         SMEM_BYTES);
    fused_k<<<NBLK, TPB, SMEM_BYTES>>>(x, Wg, bg, Wp, bp, Wa, ba, out);
}

// round 8
// speedup vs baseline: 1.1915x; 1.1915x over previous
#include <cuda_runtime.h>
#include <cuda_bf16.h>

#define TPB  256
#define NBLK 256          // 64 rows per block

// smem partition (bytes)
#define WSA_OFF 0                       // ulonglong2[2304]  cols 0-3
#define WSB_OFF 36864                   // ulonglong2[2304]  cols 4-7
#define WSC_OFF 73728                   // ulonglong2[2304]  cols 8-11
#define WSD_OFF 110592                  // ull[2176]         cols 12-13
#define SMEM_BYTES 128000

typedef unsigned long long ull;

static __device__ __forceinline__ ull pack2(float a) {
    ull r; asm("mov.b64 %0, {%1, %1};" : "=l"(r) : "f"(a)); return r;
}
static __device__ __forceinline__ void unpack2(ull v, float& a, float& b) {
    asm("mov.b64 {%0, %1}, %2;" : "=f"(a), "=f"(b) : "l"(v));
}
static __device__ __forceinline__ ull ffma2(ull a, ull b, ull c) {
    ull d; asm("fma.rn.f32x2 %0, %1, %2, %3;" : "=l"(d) : "l"(a), "l"(b), "l"(c));
    return d;
}
static __device__ __forceinline__ ull fadd2(ull a, ull b) {
    ull d; asm("add.rn.f32x2 %0, %1, %2;" : "=l"(d) : "l"(a), "l"(b));
    return d;
}
static __device__ __forceinline__ ull shfl64(ull v, int m) {
    return __shfl_xor_sync(0xffffffffu, v, m);
}

// load packed weights for one h from the padded smem arrays
static __device__ __forceinline__ void load_w(const char* smem, int h, ull w[7]) {
    int ia = h + (h >> 3);
    int id = h + (h >> 4);
    ulonglong2 a = ((const ulonglong2*)(smem + WSA_OFF))[ia];
    ulonglong2 b = ((const ulonglong2*)(smem + WSB_OFF))[ia];
    ulonglong2 c = ((const ulonglong2*)(smem + WSC_OFF))[ia];
    ull        d = ((const ull*)      (smem + WSD_OFF))[id];
    w[0] = a.x; w[1] = a.y; w[2] = b.x; w[3] = b.y; w[4] = c.x; w[5] = c.y; w[6] = d;
}

__global__ void __launch_bounds__(TPB) fused_k(
    const float* __restrict__ x,
    const float* __restrict__ Wg, const float* __restrict__ bg,
    const float* __restrict__ Wp, const float* __restrict__ bp,
    const float* __restrict__ Wa, const float* __restrict__ ba,
    float* __restrict__ out)
{
    extern __shared__ char smem[];
    const int tid = threadIdx.x;

    // ---- stage weights: one h per thread per iteration (coalesced gmem reads)
    for (int h = tid; h < 2048; h += TPB) {
        int ia = h + (h >> 3);
        int id = h + (h >> 4);
        float4 g = *(const float4*)(Wg + h * 4);
        float4 p = *(const float4*)(Wp + h * 4);
        const float* a = Wa + h * 5;
        float4 c0 = make_float4(a[0], a[1], a[2], a[3]);
        float2 d0 = make_float2(a[4], 0.f);
        ((float4*)(smem + WSA_OFF))[ia] = g;
        ((float4*)(smem + WSB_OFF))[ia] = p;
        ((float4*)(smem + WSC_OFF))[ia] = c0;
        ((float2*)(smem + WSD_OFF))[id] = d0;
    }
    __syncthreads();

    const int lane = tid & 31;
    const int warp = tid >> 5;
    const int rowbase = blockIdx.x * 64 + warp * 8;
    const float* xbase = x + (size_t)rowbase * 2048 + 2 * lane;

    ull acc[8][7];
#pragma unroll
    for (int r = 0; r < 8; r++)
#pragma unroll
        for (int k = 0; k < 7; k++) acc[r][k] = 0ull;

    for (int c = 0; c < 32; c += 2) {
        float2 x0[8], x1[8];
#pragma unroll
        for (int r = 0; r < 8; r++)
            x0[r] = __ldcs((const float2*)(xbase + (size_t)r * 2048 + c * 64));
#pragma unroll
        for (int r = 0; r < 8; r++)
            x1[r] = __ldcs((const float2*)(xbase + (size_t)r * 2048 + (c + 1) * 64));

        {   // subchunk c
            const int h0 = c * 64 + 2 * lane;
            ull wE[7], wO[7];
            load_w(smem, h0, wE);
            load_w(smem, h0 + 1, wO);
#pragma unroll
            for (int r = 0; r < 8; r++) {
                ull xe = pack2(x0[r].x);
#pragma unroll
                for (int k = 0; k < 7; k++) acc[r][k] = ffma2(xe, wE[k], acc[r][k]);
                ull xo = pack2(x0[r].y);
#pragma unroll
                for (int k = 0; k < 7; k++) acc[r][k] = ffma2(xo, wO[k], acc[r][k]);
            }
        }
        {   // subchunk c+1
            const int h0 = (c + 1) * 64 + 2 * lane;
            ull wE[7], wO[7];
            load_w(smem, h0, wE);
            load_w(smem, h0 + 1, wO);
#pragma unroll
            for (int r = 0; r < 8; r++) {
                ull xe = pack2(x1[r].x);
#pragma unroll
                for (int k = 0; k < 7; k++) acc[r][k] = ffma2(xe, wE[k], acc[r][k]);
                ull xo = pack2(x1[r].y);
#pragma unroll
                for (int k = 0; k < 7; k++) acc[r][k] = ffma2(xo, wO[k], acc[r][k]);
            }
        }
    }

    // ---- compacting butterfly reduction over the 32 lanes
    // round 1 (xor16): 8 rows -> 4 ; row bit2 = lane4
    ull a4[4][7];
#pragma unroll
    for (int r = 0; r < 4; r++)
#pragma unroll
        for (int k = 0; k < 7; k++) {
            ull lo = fadd2(acc[r][k],     shfl64(acc[r][k],     16));
            ull hi = fadd2(acc[r + 4][k], shfl64(acc[r + 4][k], 16));
            a4[r][k] = (lane & 16) ? hi : lo;
        }
    // round 2 (xor8): 4 -> 2 ; row bit1 = lane3
    ull a2[2][7];
#pragma unroll
    for (int r = 0; r < 2; r++)
#pragma unroll
        for (int k = 0; k < 7; k++) {
            ull lo = fadd2(a4[r][k],     shfl64(a4[r][k],     8));
            ull hi = fadd2(a4[r + 2][k], shfl64(a4[r + 2][k], 8));
            a2[r][k] = (lane & 8) ? hi : lo;
        }
    // round 3 (xor4): 2 -> 1 ; row bit0 = lane2
    ull a1[7];
#pragma unroll
    for (int k = 0; k < 7; k++) {
        ull lo = fadd2(a2[0][k], shfl64(a2[0][k], 4));
        ull hi = fadd2(a2[1][k], shfl64(a2[1][k], 4));
        a1[k] = (lane & 4) ? hi : lo;
    }
    // rounds 4,5: reduce remaining 4 lanes of the group
#pragma unroll
    for (int k = 0; k < 7; k++) {
        a1[k] = fadd2(a1[k], shfl64(a1[k], 2));
        a1[k] = fadd2(a1[k], shfl64(a1[k], 1));
    }

    // ---- epilogue: lanes 0,4,8,... own row = rowbase + (lane>>2)
    if ((lane & 3) == 0) {
        const int row = rowbase + (lane >> 2);
        float v[14];
#pragma unroll
        for (int k = 0; k < 7; k++) unpack2(a1[k], v[2 * k], v[2 * k + 1]);

        const float LOG2E = 1.4426950408889634f;
        float G[4], P[4], A[5];
#pragma unroll
        for (int c = 0; c < 4; c++) G[c] = v[c]     + __ldg(bg + c);
#pragma unroll
        for (int c = 0; c < 4; c++) P[c] = v[4 + c] + __ldg(bp + c);
#pragma unroll
        for (int c = 0; c < 5; c++) A[c] = v[8 + c] + __ldg(ba + c);

        float mg = fmaxf(fmaxf(G[0], G[1]), fmaxf(G[2], G[3]));
        float sg = 0.f;
#pragma unroll
        for (int c = 0; c < 4; c++) { G[c] = exp2f((G[c] - mg) * LOG2E); sg += G[c]; }
        float ig = 1.f / sg;
#pragma unroll
        for (int c = 0; c < 4; c++) G[c] *= ig;

        float mp = fmaxf(fmaxf(P[0], P[1]), fmaxf(P[2], P[3]));
        float sp = 0.f;
#pragma unroll
        for (int c = 0; c < 4; c++) { P[c] = exp2f((P[c] - mp) * LOG2E); sp += P[c]; }
        float ip = 1.f / sp;
#pragma unroll
        for (int c = 0; c < 4; c++) P[c] *= ip;

        float ma = fmaxf(fmaxf(fmaxf(A[0], A[1]), fmaxf(A[2], A[3])), A[4]);
        float sa = 0.f;
#pragma unroll
        for (int c = 0; c < 5; c++) { A[c] = exp2f((A[c] - ma) * LOG2E); sa += A[c]; }
        float ia = 1.f / sa;
#pragma unroll
        for (int c = 0; c < 5; c++) A[c] *= ia;

        float u0 = P[0] * G[0] + P[1] * G[1] + P[2] * G[2] + P[3] * G[3]; // stay
        float u1 = P[0] * G[1] + P[2] * G[3];                             // up
        float u2 = P[1] * G[0] + P[3] * G[2];                             // down

        float j0 = A[0] * (1.f - u0);
        float j1 = A[1] * (1.f - u1);
        float j2 = A[2] * (1.f - u2);
        float j3 = A[3];
        float j4 = A[4];
        float inv = 1.f / (j0 + j1 + j2 + j3 + j4);

        float* o = out + (size_t)row * 5;
        o[0] = j0 * inv; o[1] = j1 * inv; o[2] = j2 * inv;
        o[3] = j3 * inv; o[4] = j4 * inv;
    }
}

extern "C" void kernel_launch(void* const* d_in, const int* in_sizes, int n_in,
                              void* d_out, int out_size) {
    const float* x  = (const float*)d_in[0];
    const float* Wg = (const float*)d_in[1];
    const float* bg = (const float*)d_in[2];
    const float* Wp = (const float*)d_in[3];
    const float* bp = (const float*)d_in[4];
    const float* Wa = (const float*)d_in[5];
    const float* ba = (const float*)d_in[6];
    float* out = (float*)d_out;

    cudaFuncSetAttribute(fused_k, cudaFuncAttributeMaxDynamicSharedMemorySize,
                         SMEM_BYTES);
    fused_k<<<NBLK, TPB, SMEM_BYTES>>>(x, Wg, bg, Wp, bp, Wa, ba, out);
}

// round 16
// speedup vs baseline: 2.8236x; 2.3699x over previous
#include <cuda_runtime.h>
#include <cuda_bf16.h>

#define TPB  512
#define NBLK 256          // 64 rows per block (16 warps x 4 rows)

// smem partition (bytes)
#define WSA_OFF 0                       // float4[2304]  cols 0-3   (idx = h + h/8)
#define WSB_OFF 36864                   // float4[2304]  cols 4-7
#define WSC_OFF 73728                   // float4[2304]  cols 8-11
#define WSD_OFF 110592                  // float2[2176]  cols 12-13 (idx = h + h/16)
#define SMEM_BYTES 128000               // WSD ends at 110592 + 2175*8 = 127992

typedef unsigned long long ull;

static __device__ __forceinline__ ull pack2(float a) {
    ull r; asm("mov.b64 %0, {%1, %1};" : "=l"(r) : "f"(a)); return r;
}
static __device__ __forceinline__ void unpack2(ull v, float& a, float& b) {
    asm("mov.b64 {%0, %1}, %2;" : "=f"(a), "=f"(b) : "l"(v));
}
static __device__ __forceinline__ ull ffma2(ull a, ull b, ull c) {
    ull d; asm("fma.rn.f32x2 %0, %1, %2, %3;" : "=l"(d) : "l"(a), "l"(b), "l"(c));
    return d;
}
static __device__ __forceinline__ ull fadd2(ull a, ull b) {
    ull d; asm("add.rn.f32x2 %0, %1, %2;" : "=l"(d) : "l"(a), "l"(b));
    return d;
}
static __device__ __forceinline__ ull shfl64(ull v, int m) {
    return __shfl_xor_sync(0xffffffffu, v, m);
}

// load packed weights for one h from the padded smem arrays (conflict-free
// for the h = 64c + 2*lane warp pattern; verified in R8: L1 = 14%)
static __device__ __forceinline__ void load_w(const char* smem, int h, ull w[7]) {
    int ia = h + (h >> 3);
    int id = h + (h >> 4);
    ulonglong2 a = ((const ulonglong2*)(smem + WSA_OFF))[ia];
    ulonglong2 b = ((const ulonglong2*)(smem + WSB_OFF))[ia];
    ulonglong2 c = ((const ulonglong2*)(smem + WSC_OFF))[ia];
    ull        d = ((const ull*)      (smem + WSD_OFF))[id];
    w[0] = a.x; w[1] = a.y; w[2] = b.x; w[3] = b.y; w[4] = c.x; w[5] = c.y; w[6] = d;
}

__global__ void __launch_bounds__(TPB) fused_k(
    const float* __restrict__ x,
    const float* __restrict__ Wg, const float* __restrict__ bg,
    const float* __restrict__ Wp, const float* __restrict__ bp,
    const float* __restrict__ Wa, const float* __restrict__ ba,
    float* __restrict__ out)
{
    extern __shared__ char smem[];
    const int tid = threadIdx.x;

    // ---- stage weights (coalesced; 4 h per thread)
    for (int h = tid; h < 2048; h += TPB) {
        int ia = h + (h >> 3);
        int id = h + (h >> 4);
        float4 g = *(const float4*)(Wg + h * 4);
        float4 p = *(const float4*)(Wp + h * 4);
        const float* a = Wa + h * 5;
        ((float4*)(smem + WSA_OFF))[ia] = g;
        ((float4*)(smem + WSB_OFF))[ia] = p;
        ((float4*)(smem + WSC_OFF))[ia] = make_float4(a[0], a[1], a[2], a[3]);
        ((float2*)(smem + WSD_OFF))[id] = make_float2(a[4], 0.f);
    }
    __syncthreads();

    const int lane = tid & 31;
    const int warp = tid >> 5;
    const int rowbase = blockIdx.x * 64 + warp * 4;       // 4 rows per warp
    const float* xp = x + (size_t)rowbase * 2048 + 2 * lane;

    ull acc[4][7];
#pragma unroll
    for (int r = 0; r < 4; r++)
#pragma unroll
        for (int k = 0; k < 7; k++) acc[r][k] = 0ull;

    // double-buffered prefetch of the 4 row-loads
    float2 xb[2][4];
#pragma unroll
    for (int r = 0; r < 4; r++)
        xb[0][r] = __ldcs((const float2*)(xp + (size_t)r * 2048));

#pragma unroll 2
    for (int c = 0; c < 32; c++) {
        const int cur = c & 1;
        if (c < 31) {
            const float* xn = xp + 64;
#pragma unroll
            for (int r = 0; r < 4; r++)
                xb[cur ^ 1][r] = __ldcs((const float2*)(xn + (size_t)r * 2048));
        }
        xp += 64;

        const int h0 = c * 64 + 2 * lane;
        ull wE[7], wO[7];
        load_w(smem, h0,     wE);
        load_w(smem, h0 + 1, wO);

#pragma unroll
        for (int r = 0; r < 4; r++) {
            ull xe = pack2(xb[cur][r].x);
#pragma unroll
            for (int k = 0; k < 7; k++) acc[r][k] = ffma2(xe, wE[k], acc[r][k]);
            ull xo = pack2(xb[cur][r].y);
#pragma unroll
            for (int k = 0; k < 7; k++) acc[r][k] = ffma2(xo, wO[k], acc[r][k]);
        }
    }

    // ---- compacting butterfly reduction (4 rows -> 1 per 8-lane group)
    ull a2[2][7];
#pragma unroll
    for (int r = 0; r < 2; r++)
#pragma unroll
        for (int k = 0; k < 7; k++) {
            ull lo = fadd2(acc[r][k],     shfl64(acc[r][k],     16));
            ull hi = fadd2(acc[r + 2][k], shfl64(acc[r + 2][k], 16));
            a2[r][k] = (lane & 16) ? hi : lo;
        }
    ull a1[7];
#pragma unroll
    for (int k = 0; k < 7; k++) {
        ull lo = fadd2(a2[0][k], shfl64(a2[0][k], 8));
        ull hi = fadd2(a2[1][k], shfl64(a2[1][k], 8));
        a1[k] = (lane & 8) ? hi : lo;
    }
#pragma unroll
    for (int k = 0; k < 7; k++) {
        a1[k] = fadd2(a1[k], shfl64(a1[k], 4));
        a1[k] = fadd2(a1[k], shfl64(a1[k], 2));
        a1[k] = fadd2(a1[k], shfl64(a1[k], 1));
    }

    // ---- epilogue: lanes 0,8,16,24 own row = rowbase + (lane>>3)
    if ((lane & 7) == 0) {
        const int row = rowbase + (lane >> 3);
        float v[14];
#pragma unroll
        for (int k = 0; k < 7; k++) unpack2(a1[k], v[2 * k], v[2 * k + 1]);

        const float LOG2E = 1.4426950408889634f;
        float G[4], P[4], A[5];
#pragma unroll
        for (int c = 0; c < 4; c++) G[c] = v[c]     + __ldg(bg + c);
#pragma unroll
        for (int c = 0; c < 4; c++) P[c] = v[4 + c] + __ldg(bp + c);
#pragma unroll
        for (int c = 0; c < 5; c++) A[c] = v[8 + c] + __ldg(ba + c);

        float mg = fmaxf(fmaxf(G[0], G[1]), fmaxf(G[2], G[3]));
        float sg = 0.f;
#pragma unroll
        for (int c = 0; c < 4; c++) { G[c] = exp2f((G[c] - mg) * LOG2E); sg += G[c]; }
        float ig = 1.f / sg;
#pragma unroll
        for (int c = 0; c < 4; c++) G[c] *= ig;

        float mp = fmaxf(fmaxf(P[0], P[1]), fmaxf(P[2], P[3]));
        float sp = 0.f;
#pragma unroll
        for (int c = 0; c < 4; c++) { P[c] = exp2f((P[c] - mp) * LOG2E); sp += P[c]; }
        float ip = 1.f / sp;
#pragma unroll
        for (int c = 0; c < 4; c++) P[c] *= ip;

        float ma = fmaxf(fmaxf(fmaxf(A[0], A[1]), fmaxf(A[2], A[3])), A[4]);
        float sa = 0.f;
#pragma unroll
        for (int c = 0; c < 5; c++) { A[c] = exp2f((A[c] - ma) * LOG2E); sa += A[c]; }
        float ia = 1.f / sa;
#pragma unroll
        for (int c = 0; c < 5; c++) A[c] *= ia;

        float u0 = P[0] * G[0] + P[1] * G[1] + P[2] * G[2] + P[3] * G[3]; // stay
        float u1 = P[0] * G[1] + P[2] * G[3];                             // up
        float u2 = P[1] * G[0] + P[3] * G[2];                             // down

        float j0 = A[0] * (1.f - u0);
        float j1 = A[1] * (1.f - u1);
        float j2 = A[2] * (1.f - u2);
        float j3 = A[3];
        float j4 = A[4];
        float inv = 1.f / (j0 + j1 + j2 + j3 + j4);

        float* o = out + (size_t)row * 5;
        o[0] = j0 * inv; o[1] = j1 * inv; o[2] = j2 * inv;
        o[3] = j3 * inv; o[4] = j4 * inv;
    }
}

extern "C" void kernel_launch(void* const* d_in, const int* in_sizes, int n_in,
                              void* d_out, int out_size) {
    const float* x  = (const float*)d_in[0];
    const float* Wg = (const float*)d_in[1];
    const float* bg = (const float*)d_in[2];
    const float* Wp = (const float*)d_in[3];
    const float* bp = (const float*)d_in[4];
    const float* Wa = (const float*)d_in[5];
    const float* ba = (const float*)d_in[6];
    float* out = (float*)d_out;

    cudaFuncSetAttribute(fused_k, cudaFuncAttributeMaxDynamicSharedMemorySize,
                         SMEM_BYTES);
    fused_k<<<NBLK, TPB, SMEM_BYTES>>>(x, Wg, bg, Wp, bp, Wa, ba, out);
}